// round 11
// baseline (speedup 1.0000x reference)
#include <cuda_runtime.h>
#include <cuda_bf16.h>

// PersistenceLandscapeLayer — warp-autonomous pipeline, split-P, last-CTA merge.
// Each warp: gather 64 pairs -> filter -> per-warp ballot-compaction (register
// counters, no atomics, no CTA barrier) -> scan own survivors with one (d,t)
// cell per lane (lane t owns dim0&dim1 cells) using 4 independent insert
// chains. Warp partials tree-merged in smem; last CTA per row merges S chunks.
//
// tent(t) = max(min(t-b, d-t), 0) == max(hw - |t-c|, 0). Clamp dropped: top-4
// regs start at 0, stay >= 0, negatives never enter (fmax rejects per rung).

constexpr int TT    = 32;
constexpr int D_HOM = 2;
constexpr int KMAX  = 4;
constexpr int NCELL = D_HOM * TT;            // 64
constexpr int NTH   = 256;
constexpr int NWARP = NTH / 32;              // 8
constexpr int PPW   = 64;                    // pairs per warp (2 per lane)
constexpr int CHUNK = NWARP * PPW;           // 512 pairs per CTA
constexpr int MAXB  = 128;
constexpr int MAXS  = 16;                    // P up to 8192
constexpr unsigned FULL = 0xffffffffu;

__device__ float4 g_part[MAXB * MAXS * NCELL];   // 2MB scratch
__device__ int    g_cnt[MAXB];                   // zero-init; reset by last CTA

// Insert v into sorted-desc quad (r0>=r1>=r2>=r3).
#define INS4(r0,r1,r2,r3,v) do { float _x;                         \
    _x = fmaxf(r0, v); v = fminf(r0, v); r0 = _x;                  \
    _x = fmaxf(r1, v); v = fminf(r1, v); r1 = _x;                  \
    _x = fmaxf(r2, v); v = fminf(r2, v); r2 = _x;                  \
    r3 = fmaxf(r3, v); } while (0)

// a := top-4 of two sorted-desc quads (bitonic max-half + sort4 desc).
#define BMERGE(a0,a1,a2,a3,b0,b1,b2,b3) do {                       \
    float _l0 = fmaxf(a0, b3), _l1 = fmaxf(a1, b2);                \
    float _l2 = fmaxf(a2, b1), _l3 = fmaxf(a3, b0);                \
    float _x0 = fmaxf(_l0, _l2), _x2 = fminf(_l0, _l2);            \
    float _x1 = fmaxf(_l1, _l3), _x3 = fminf(_l1, _l3);            \
    a0 = fmaxf(_x0, _x1); a1 = fminf(_x0, _x1);                    \
    a2 = fmaxf(_x2, _x3); a3 = fminf(_x2, _x3); } while (0)

__device__ __forceinline__ float4 bmerge4(float4 a, float4 b) {
    BMERGE(a.x, a.y, a.z, a.w, b.x, b.y, b.z, b.w);
    return a;
}

__global__ __launch_bounds__(NTH)
void pl_fused(const float* __restrict__ fun,
              const int*   __restrict__ bidx,
              const int*   __restrict__ didx,
              const int*   __restrict__ pdim,
              float*       __restrict__ out,
              int N, int P, int S)
{
    __shared__ float2 wlst[NWARP][D_HOM][PPW];   // warp-private survivor lists
    __shared__ float4 mbuf[NWARP][NCELL];        // per-warp cell partials
    __shared__ int    isLast;

    const int tid  = threadIdx.x;
    const int lane = tid & 31;
    const int wp   = tid >> 5;
    const int ss   = blockIdx.x;                 // split
    const int bb   = blockIdx.y;                 // batch row

    const float* frow = fun  + (size_t)bb * N;
    const int*   brow = bidx + (size_t)bb * P;
    const int*   drow = didx + (size_t)bb * P;
    const int*   prow = pdim + (size_t)bb * P;

    // ---- Gather (2 pairs/lane, all scattered loads in flight together) ----
    const int p0  = ss * CHUNK + wp * PPW + 2 * lane;
    bool act0 = (p0     < P);
    bool act1 = (p0 + 1 < P);
    int  bi0 = 0, bi1 = 0, di0 = 0, di1 = 0, dm0 = 0, dm1 = 0;
    if (act1) {
        int2 b2 = *(const int2*)(brow + p0);
        int2 d2 = *(const int2*)(drow + p0);
        int2 m2 = *(const int2*)(prow + p0);
        bi0 = b2.x; bi1 = b2.y; di0 = d2.x; di1 = d2.y; dm0 = m2.x; dm1 = m2.y;
    } else if (act0) {
        bi0 = brow[p0]; di0 = drow[p0]; dm0 = prow[p0];
    }
    float bv0 = 0.f, dv0 = 0.f, bv1 = 0.f, dv1 = 0.f;
    if (act0) { bv0 = __ldcg(frow + bi0); dv0 = __ldcg(frow + di0); }
    if (act1) { bv1 = __ldcg(frow + bi1); dv1 = __ldcg(frow + di1); }

    bool keep0 = act0 && (dv0 > bv0);
    bool keep1 = act1 && (dv1 > bv1);
    float c0 = (bv0 + dv0) * 0.5f, h0 = (dv0 - bv0) * 0.5f;
    float c1 = (bv1 + dv1) * 0.5f, h1 = (dv1 - bv1) * 0.5f;

    // ---- Per-warp compaction: register counters, no atomics, no barrier ----
    int n0 = 0, n1 = 0;
    {
        const unsigned lt = (1u << lane) - 1u;
        unsigned m;
        m = __ballot_sync(FULL, keep0 && dm0 == 0);
        if (keep0 && dm0 == 0) wlst[wp][0][n0 + __popc(m & lt)] = make_float2(c0, h0);
        n0 += __popc(m);
        m = __ballot_sync(FULL, keep1 && dm1 == 0);
        if (keep1 && dm1 == 0) wlst[wp][0][n0 + __popc(m & lt)] = make_float2(c1, h1);
        n0 += __popc(m);
        m = __ballot_sync(FULL, keep0 && dm0 == 1);
        if (keep0 && dm0 == 1) wlst[wp][1][n1 + __popc(m & lt)] = make_float2(c0, h0);
        n1 += __popc(m);
        m = __ballot_sync(FULL, keep1 && dm1 == 1);
        if (keep1 && dm1 == 1) wlst[wp][1][n1 + __popc(m & lt)] = make_float2(c1, h1);
        n1 += __popc(m);
    }
    __syncwarp();

    // ---- Scan: lane owns cells (dim0, t=lane) and (dim1, t=lane). ----
    // 4 independent insert chains: dim x k-parity. Out-of-range reads are
    // masked to -1 (selected below), so uninitialized smem cannot matter.
    const float tv = (float)(lane + 1) * (1.0f / (float)TT);
    float A0=0.f,A1=0.f,A2=0.f,A3=0.f;   // dim0, even k
    float B0=0.f,B1=0.f,B2=0.f,B3=0.f;   // dim0, odd k
    float C0=0.f,C1=0.f,C2=0.f,C3=0.f;   // dim1, even k
    float D0=0.f,D1=0.f,D2=0.f,D3=0.f;   // dim1, odd k

    const int kmax = max(n0, n1);
    for (int k = 0; k < kmax; k += 2) {
        const int k1 = min(k + 1, PPW - 1);          // stay in-bounds
        float2 qa0 = wlst[wp][0][k];
        float2 qb0 = wlst[wp][0][k1];
        float2 qa1 = wlst[wp][1][k];
        float2 qb1 = wlst[wp][1][k1];
        float ma0 = qa0.y - fabsf(tv - qa0.x); ma0 = (k     < n0) ? ma0 : -1.0f;
        float mb0 = qb0.y - fabsf(tv - qb0.x); mb0 = (k + 1 < n0) ? mb0 : -1.0f;
        float ma1 = qa1.y - fabsf(tv - qa1.x); ma1 = (k     < n1) ? ma1 : -1.0f;
        float mb1 = qb1.y - fabsf(tv - qb1.x); mb1 = (k + 1 < n1) ? mb1 : -1.0f;
        INS4(A0, A1, A2, A3, ma0);
        INS4(B0, B1, B2, B3, mb0);
        INS4(C0, C1, C2, C3, ma1);
        INS4(D0, D1, D2, D3, mb1);
    }
    BMERGE(A0, A1, A2, A3, B0, B1, B2, B3);          // dim0 result in A
    BMERGE(C0, C1, C2, C3, D0, D1, D2, D3);          // dim1 result in C

    mbuf[wp][lane]      = make_float4(A0, A1, A2, A3);
    mbuf[wp][32 + lane] = make_float4(C0, C1, C2, C3);
    __syncthreads();                                 // only CTA-wide barrier

    // ---- Combine 8 warp partials per cell; write chunk partial ----
    if (tid < NCELL) {
        float4 r = bmerge4(bmerge4(bmerge4(mbuf[0][tid], mbuf[1][tid]),
                                   bmerge4(mbuf[2][tid], mbuf[3][tid])),
                           bmerge4(bmerge4(mbuf[4][tid], mbuf[5][tid]),
                                   bmerge4(mbuf[6][tid], mbuf[7][tid])));
        g_part[((size_t)bb * S + ss) * NCELL + tid] = r;
        __threadfence();                             // partial visible device-wide
    }
    __syncthreads();                                 // fences before tid0 atomic

    // ---- Last CTA of this batch row merges the S chunk partials ----
    if (tid == 0) {
        int v = atomicAdd(&g_cnt[bb], 1);
        isLast = (v == S - 1);
        if (isLast) g_cnt[bb] = 0;                   // reset for graph replay
    }
    __syncthreads();

    if (isLast) {
        if (tid == 0) __threadfence();               // acquire side
        __syncthreads();
        if (tid < NCELL) {
            const float4* src = &g_part[(size_t)bb * S * NCELL + tid];
            float4 r = __ldcg(src);                  // bypass stale L1
            for (int s = 1; s < S; ++s)
                r = bmerge4(r, __ldcg(src + (size_t)s * NCELL));
            ((float4*)out)[(size_t)bb * NCELL + tid] = r;
        }
    }
}

extern "C" void kernel_launch(void* const* d_in, const int* in_sizes, int n_in,
                              void* d_out, int out_size)
{
    const float* fun = (const float*)d_in[0];
    const int*   bi  = (const int*)  d_in[1];
    const int*   di  = (const int*)  d_in[2];
    const int*   pd  = (const int*)  d_in[3];
    float*       out = (float*)d_out;

    int B = out_size / (D_HOM * TT * KMAX);
    int N = in_sizes[0] / B;
    int P = in_sizes[1] / B;
    int S = (P + CHUNK - 1) / CHUNK;                 // 8 for P=4096
    if (S > MAXS) S = MAXS;                          // scratch bound

    dim3 g(S, B);
    pl_fused<<<g, NTH>>>(fun, bi, di, pd, out, N, P, S);
}